// round 13
// baseline (speedup 1.0000x reference)
#include <cuda_runtime.h>
#include <cstdint>

// ---------------------------------------------------------------------------
// out[i] = sum_{e: w_rows[e]==i} Param_W[w_params[e]] * x[w_cols[e]]
//          + Param_b[b_params[i]]
//
// N = 262144, E = 16.7M. Edge scatter (16384x256, 4 edges/thread, fp32,
// __ldg) is at 97% of the L1tex-wavefront ceiling — established floor over
// 11 ablations (no smem, no fp16, no persistence, no DSMEM). R13 removes the
// last overhead: the bias epilogue is folded into the SAME kernel via a
// grid-completion ticket — the last 256 finishing CTAs wait for all REDs,
// then compute out = g_acc + bias and re-zero g_acc + counters (replay-safe).
// ---------------------------------------------------------------------------

#define NMAX     262144
#define EPI_CTAS 256          // last-256 finishers run the epilogue
#define EDGE_T   256

__device__ float g_acc[NMAX];       // zero at load; re-zeroed every call
__device__ int   g_done  = 0;       // CTA completion ticket counter
__device__ int   g_done2 = 0;       // epilogue completion counter

__global__ void __launch_bounds__(EDGE_T)
edge_fused_kernel(const float* __restrict__ x,
                  const float* __restrict__ Param_W,
                  const float* __restrict__ Param_b,
                  const int4*  __restrict__ rows4,
                  const int4*  __restrict__ cols4,
                  const int4*  __restrict__ params4,
                  const int4*  __restrict__ b_params4,
                  float4*      __restrict__ out4,
                  int E4, int N4)
{
    // ---- phase 1: edge quad (proven optimal shape) ----
    int t = blockIdx.x * EDGE_T + threadIdx.x;
    if (t < E4) {
        int4 r = __ldcs(&rows4[t]);
        int4 c = __ldcs(&cols4[t]);
        int4 p = __ldcs(&params4[t]);

        float v0 = __ldg(&Param_W[p.x]) * __ldg(&x[c.x]);
        float v1 = __ldg(&Param_W[p.y]) * __ldg(&x[c.y]);
        float v2 = __ldg(&Param_W[p.z]) * __ldg(&x[c.z]);
        float v3 = __ldg(&Param_W[p.w]) * __ldg(&x[c.w]);

        atomicAdd(&g_acc[r.x], v0);
        atomicAdd(&g_acc[r.y], v1);
        atomicAdd(&g_acc[r.z], v2);
        atomicAdd(&g_acc[r.w], v3);
    }

    // ---- phase 2: grid-completion ticket ----
    __shared__ int s_ticket;
    if (threadIdx.x == 0) {
        __threadfence();                       // make this CTA's REDs visible
        s_ticket = atomicAdd(&g_done, 1);
    }
    __syncthreads();

    int G = gridDim.x;
    int ticket = s_ticket;
    if (ticket < G - EPI_CTAS) return;         // early finishers exit

    // ---- phase 3: last EPI_CTAS finishers wait for the whole grid ----
    if (threadIdx.x == 0) {
        while (*(volatile int*)&g_done < G) __nanosleep(64);
    }
    __syncthreads();
    __threadfence();                           // acquire: g_acc now complete

    // ---- phase 4: epilogue slice  out = acc + bias; acc = 0 ----
    int rank = ticket - (G - EPI_CTAS);        // 0..EPI_CTAS-1
    int per  = N4 / EPI_CTAS;
    int lo   = rank * per;
    int hi   = (rank == EPI_CTAS - 1) ? N4 : lo + per;
    for (int j = lo + threadIdx.x; j < hi; j += EDGE_T) {
        float4* acc4 = (float4*)&g_acc[j * 4];
        float4 a = *acc4;
        int4   b = __ldg(&b_params4[j]);
        float4 o;
        o.x = a.x + __ldg(&Param_b[b.x]);
        o.y = a.y + __ldg(&Param_b[b.y]);
        o.z = a.z + __ldg(&Param_b[b.z]);
        o.w = a.w + __ldg(&Param_b[b.w]);
        out4[j] = o;
        *acc4 = make_float4(0.f, 0.f, 0.f, 0.f);
    }

    // ---- phase 5: last epilogue CTA resets counters (replay-safe) ----
    __syncthreads();
    if (threadIdx.x == 0) {
        __threadfence();
        int t2 = atomicAdd(&g_done2, 1);
        if (t2 == EPI_CTAS - 1) {
            g_done  = 0;
            g_done2 = 0;
            __threadfence();
        }
    }
}

// ---------- fallback path (shapes not matching the fused assumptions) ------
__global__ void bias_only_kernel(const float* __restrict__ Param_b,
                                 const int*   __restrict__ b_params,
                                 float*       __restrict__ out, int N)
{
    int i = blockIdx.x * blockDim.x + threadIdx.x;
    if (i < N) out[i] = __ldg(&Param_b[b_params[i]]);
}

__global__ void edge_scatter_direct_kernel(const float* __restrict__ x,
                                           const float* __restrict__ Param_W,
                                           const int*   __restrict__ rows,
                                           const int*   __restrict__ cols,
                                           const int*   __restrict__ params,
                                           float*       __restrict__ out,
                                           int E)
{
    int e = blockIdx.x * blockDim.x + threadIdx.x;
    if (e < E) {
        float v = __ldg(&Param_W[params[e]]) * __ldg(&x[cols[e]]);
        atomicAdd(&out[rows[e]], v);
    }
}

extern "C" void kernel_launch(void* const* d_in, const int* in_sizes, int n_in,
                              void* d_out, int out_size)
{
    const float* x        = (const float*)d_in[0];
    const float* Param_W  = (const float*)d_in[1];
    const float* Param_b  = (const float*)d_in[2];
    const int*   w_rows   = (const int*)  d_in[3];
    const int*   w_cols   = (const int*)  d_in[4];
    const int*   w_params = (const int*)  d_in[5];
    const int*   b_params = (const int*)  d_in[6];
    float*       out      = (float*)d_out;

    const int N = out_size;       // 262144
    const int E = in_sizes[3];    // 16777216

    int E4 = E / 4;
    int N4 = N / 4;
    int G  = (E4 + EDGE_T - 1) / EDGE_T;      // 16384

    bool fused_ok = (N <= NMAX) && (E % 4 == 0) && (N % 4 == 0) &&
                    (G > 2 * EPI_CTAS) && (N4 >= EPI_CTAS);

    if (fused_ok) {
        edge_fused_kernel<<<G, EDGE_T>>>(
            x, Param_W, Param_b,
            (const int4*)w_rows, (const int4*)w_cols, (const int4*)w_params,
            (const int4*)b_params, (float4*)out, E4, N4);
    } else {
        // Safe two-pass fallback: bias init, then direct atomic scatter.
        bias_only_kernel<<<(N + 255) / 256, 256>>>(Param_b, b_params, out, N);
        edge_scatter_direct_kernel<<<(E + 255) / 256, 256>>>(
            x, Param_W, w_rows, w_cols, w_params, out, E);
    }
}

// round 14
// speedup vs baseline: 1.4589x; 1.4589x over previous
#include <cuda_runtime.h>
#include <cstdint>

// ---------------------------------------------------------------------------
// out[i] = sum_{e: w_rows[e]==i} Param_W[w_params[e]] * x[w_cols[e]]
//          + Param_b[b_params[i]]
//
// N = 262144, E = 16.7M. Edge scatter (16384x256, 4 edges/thread, fp32 REDs
// into __device__ g_acc) is at 97% of the L1tex-wavefront ceiling — final.
// R14: epilogue launched with PDL (programmatic stream serialization). It
// front-loads the bias gathers BEFORE cudaGridDependencySynchronize(), so
// launch latency + bias loads overlap the edge kernel's drain; only the
// g_acc read + store + reset (~1-2us) remains exposed.
// ---------------------------------------------------------------------------

#define NMAX   262144
#define EDGE_T 256

__device__ float g_acc[NMAX];   // zero at load; epilogue restores zero

// --- edge scatter: proven-optimal shape, target g_acc ----------------------
__global__ void __launch_bounds__(EDGE_T)
edge_scatter_vec4_kernel(const float* __restrict__ x,
                         const float* __restrict__ Param_W,
                         const int4*  __restrict__ rows4,
                         const int4*  __restrict__ cols4,
                         const int4*  __restrict__ params4,
                         int E4)
{
    int t = blockIdx.x * EDGE_T + threadIdx.x;
    if (t >= E4) return;

    int4 r = __ldcs(&rows4[t]);
    int4 c = __ldcs(&cols4[t]);
    int4 p = __ldcs(&params4[t]);

    float v0 = __ldg(&Param_W[p.x]) * __ldg(&x[c.x]);
    float v1 = __ldg(&Param_W[p.y]) * __ldg(&x[c.y]);
    float v2 = __ldg(&Param_W[p.z]) * __ldg(&x[c.z]);
    float v3 = __ldg(&Param_W[p.w]) * __ldg(&x[c.w]);

    atomicAdd(&g_acc[r.x], v0);
    atomicAdd(&g_acc[r.y], v1);
    atomicAdd(&g_acc[r.z], v2);
    atomicAdd(&g_acc[r.w], v3);
    // Implicit PDL completion trigger fires at grid end (all REDs visible).
}

// --- PDL epilogue: bias gathers BEFORE the dependency sync -----------------
__global__ void __launch_bounds__(256)
epilogue_pdl_kernel(const float* __restrict__ Param_b,
                    const int4*  __restrict__ b_params4,
                    float4*      __restrict__ out4,
                    int N4)
{
    int i = blockIdx.x * blockDim.x + threadIdx.x;

    // Phase A (overlaps the edge kernel's drain): gather bias into registers.
    float4 bias = make_float4(0.f, 0.f, 0.f, 0.f);
    if (i < N4) {
        int4 b = __ldg(&b_params4[i]);
        bias.x = __ldg(&Param_b[b.x]);
        bias.y = __ldg(&Param_b[b.y]);
        bias.z = __ldg(&Param_b[b.z]);
        bias.w = __ldg(&Param_b[b.w]);
    }

    // Wait for the edge grid to fully complete (its REDs are then visible).
    cudaGridDependencySynchronize();

    // Phase B (exposed tail): out = acc + bias; acc = 0.
    if (i < N4) {
        float4* acc4 = (float4*)&g_acc[i * 4];
        float4 a = *acc4;
        float4 o;
        o.x = a.x + bias.x;
        o.y = a.y + bias.y;
        o.z = a.z + bias.z;
        o.w = a.w + bias.w;
        out4[i] = o;
        *acc4 = make_float4(0.f, 0.f, 0.f, 0.f);
    }
}

// --- fallback path (shape mismatch): plain two-pass ------------------------
__global__ void bias_only_kernel(const float* __restrict__ Param_b,
                                 const int*   __restrict__ b_params,
                                 float*       __restrict__ out, int N)
{
    int i = blockIdx.x * blockDim.x + threadIdx.x;
    if (i < N) out[i] = __ldg(&Param_b[b_params[i]]);
}

__global__ void edge_scatter_direct_kernel(const float* __restrict__ x,
                                           const float* __restrict__ Param_W,
                                           const int*   __restrict__ rows,
                                           const int*   __restrict__ cols,
                                           const int*   __restrict__ params,
                                           float*       __restrict__ out,
                                           int E)
{
    int e = blockIdx.x * blockDim.x + threadIdx.x;
    if (e < E) {
        float v = __ldg(&Param_W[params[e]]) * __ldg(&x[cols[e]]);
        atomicAdd(&out[rows[e]], v);
    }
}

extern "C" void kernel_launch(void* const* d_in, const int* in_sizes, int n_in,
                              void* d_out, int out_size)
{
    const float* x        = (const float*)d_in[0];
    const float* Param_W  = (const float*)d_in[1];
    const float* Param_b  = (const float*)d_in[2];
    const int*   w_rows   = (const int*)  d_in[3];
    const int*   w_cols   = (const int*)  d_in[4];
    const int*   w_params = (const int*)  d_in[5];
    const int*   b_params = (const int*)  d_in[6];
    float*       out      = (float*)d_out;

    const int N = out_size;       // 262144
    const int E = in_sizes[3];    // 16777216

    bool fused_ok = (N <= NMAX) && (E % 4 == 0) && (N % 4 == 0);

    if (!fused_ok) {
        bias_only_kernel<<<(N + 255) / 256, 256>>>(Param_b, b_params, out, N);
        edge_scatter_direct_kernel<<<(E + 255) / 256, 256>>>(
            x, Param_W, w_rows, w_cols, w_params, out, E);
        return;
    }

    int E4 = E / 4;
    int N4 = N / 4;

    // 1) Edge scatter into g_acc (zero on entry).
    {
        int blocks = (E4 + EDGE_T - 1) / EDGE_T;   // 16384
        edge_scatter_vec4_kernel<<<blocks, EDGE_T>>>(
            x, Param_W,
            (const int4*)w_rows, (const int4*)w_cols, (const int4*)w_params,
            E4);
    }

    // 2) Epilogue with Programmatic Dependent Launch: overlaps launch latency
    //    and bias gathers with the edge kernel's drain.
    {
        int threads = 256;
        int blocks  = (N4 + threads - 1) / threads;  // 256

        cudaLaunchConfig_t cfg = {};
        cfg.gridDim  = dim3((unsigned)blocks, 1, 1);
        cfg.blockDim = dim3((unsigned)threads, 1, 1);
        cfg.dynamicSmemBytes = 0;
        cfg.stream = 0;

        cudaLaunchAttribute attrs[1];
        attrs[0].id = cudaLaunchAttributeProgrammaticStreamSerialization;
        attrs[0].val.programmaticStreamSerializationAllowed = 1;
        cfg.attrs    = attrs;
        cfg.numAttrs = 1;

        cudaError_t err = cudaLaunchKernelEx(&cfg, epilogue_pdl_kernel,
                                             Param_b, (const int4*)b_params,
                                             (float4*)out, N4);
        if (err != cudaSuccess) {
            // PDL unavailable: plain launch (still correct, stream-ordered).
            epilogue_pdl_kernel<<<blocks, threads>>>(
                Param_b, (const int4*)b_params, (float4*)out, N4);
        }
    }
}